// round 12
// baseline (speedup 1.0000x reference)
#include <cuda_runtime.h>
#include <cuda_bf16.h>
#include <math.h>
#include <stdint.h>

// Problem shape (fixed by setup_inputs)
#define B_ 4
#define S_ 4096
#define H_ 768
#define E_ 64

typedef __nv_bfloat16 bf16;
typedef long long ll;

// ---------------------------------------------------------------------------
// Health flags (device-data-derived => deterministic across calls/replays)
// ---------------------------------------------------------------------------
__device__ int g_f1;   // 1 = mma pipeline healthy (selftest + qkv + scores checks)
__device__ int g_f2;   // 1 = mma PV stage healthy

// ---------------------------------------------------------------------------
// Scratch (allocation-free per harness rules)
// ---------------------------------------------------------------------------
__device__ __align__(256) float g_q[(size_t)B_ * S_ * H_];
__device__ __align__(256) float g_k[(size_t)B_ * S_ * H_];
__device__ __align__(256) float g_v[(size_t)B_ * S_ * H_];
__device__ __align__(256) float g_scores[(size_t)B_ * S_ * S_];   // 256 MB
__device__ __align__(256) float g_colbias[B_ * S_];

__device__ __align__(256) bf16 g_hshi[(size_t)B_ * S_ * H_], g_hslo[(size_t)B_ * S_ * H_];
__device__ __align__(256) bf16 g_wqhi[H_ * H_], g_wqlo[H_ * H_];
__device__ __align__(256) bf16 g_wkhi[H_ * H_], g_wklo[H_ * H_];
__device__ __align__(256) bf16 g_wvhi[H_ * H_], g_wvlo[H_ * H_];
__device__ __align__(256) bf16 g_qhi[(size_t)B_ * S_ * H_], g_qlo[(size_t)B_ * S_ * H_];
__device__ __align__(256) bf16 g_khi[(size_t)B_ * S_ * H_], g_klo[(size_t)B_ * S_ * H_];
__device__ __align__(256) bf16 g_vhi[(size_t)B_ * S_ * H_], g_vlo[(size_t)B_ * S_ * H_];
__device__ __align__(256) bf16 g_vthi[(size_t)B_ * S_ * H_], g_vtlo[(size_t)B_ * S_ * H_];
__device__ __align__(256) bf16 g_phi[(size_t)B_ * S_ * S_], g_plo[(size_t)B_ * S_ * S_];

// ---------------------------------------------------------------------------
// Helpers
// ---------------------------------------------------------------------------
__device__ __forceinline__ void mma16816(float* c, const uint32_t* a,
                                         uint32_t b0, uint32_t b1) {
    asm volatile("mma.sync.aligned.m16n8k16.row.col.f32.bf16.bf16.f32 "
                 "{%0,%1,%2,%3}, {%4,%5,%6,%7}, {%8,%9}, {%0,%1,%2,%3};"
                 : "+f"(c[0]), "+f"(c[1]), "+f"(c[2]), "+f"(c[3])
                 : "r"(a[0]), "r"(a[1]), "r"(a[2]), "r"(a[3]), "r"(b0), "r"(b1));
}
__device__ __forceinline__ uint32_t pack_bf2(float x, float y) {
    __nv_bfloat162 h = __floats2bfloat162_rn(x, y);
    return *reinterpret_cast<uint32_t*>(&h);
}
__device__ __forceinline__ void store_split(bf16* Chi, bf16* Clo, ll off,
                                            float v0, float v1) {
    bf16 h0 = __float2bfloat16(v0), h1 = __float2bfloat16(v1);
    float l0 = v0 - __bfloat162float(h0), l1 = v1 - __bfloat162float(h1);
    *reinterpret_cast<uint32_t*>(Chi + off) = pack_bf2(__bfloat162float(h0), __bfloat162float(h1));
    *reinterpret_cast<uint32_t*>(Clo + off) = pack_bf2(l0, l1);
}

// ---------------------------------------------------------------------------
// 0) flag init + register-only mma self-test (no smem, no ldmatrix)
// ---------------------------------------------------------------------------
__global__ void flag_init_kernel() { g_f1 = 1; g_f2 = 1; }

__device__ __forceinline__ float st_Af(int r, int k) { return (float)(((r * 3 + k) % 7) - 3); }
__device__ __forceinline__ float st_Bf(int n, int k) { return (float)(((n + 2 * k) % 5) - 2); }

__global__ void selftest_mma()
{
    const int lane = threadIdx.x;
    if (lane >= 32) return;
    const int g = lane >> 2, t2 = (lane & 3) * 2;
    // A[16x16], B[8(n)x16(k)] small exact ints
    uint32_t a[4];
    a[0] = pack_bf2(st_Af(g, t2),         st_Af(g, t2 + 1));
    a[1] = pack_bf2(st_Af(g + 8, t2),     st_Af(g + 8, t2 + 1));
    a[2] = pack_bf2(st_Af(g, t2 + 8),     st_Af(g, t2 + 9));
    a[3] = pack_bf2(st_Af(g + 8, t2 + 8), st_Af(g + 8, t2 + 9));
    const uint32_t b0 = pack_bf2(st_Bf(g, t2),     st_Bf(g, t2 + 1));
    const uint32_t b1 = pack_bf2(st_Bf(g, t2 + 8), st_Bf(g, t2 + 9));
    float c[4] = {0.f, 0.f, 0.f, 0.f};
    mma16816(c, a, b0, b1);
    // reference (exact): C[r][n] = sum_k A[r][k]*B[n][k]; c0/c1:(g, t2/t2+1) c2/c3:(g+8, ..)
    float ref[4] = {0.f, 0.f, 0.f, 0.f};
    for (int k = 0; k < 16; k++) {
        ref[0] += st_Af(g, k) * st_Bf(t2, k);
        ref[1] += st_Af(g, k) * st_Bf(t2 + 1, k);
        ref[2] += st_Af(g + 8, k) * st_Bf(t2, k);
        ref[3] += st_Af(g + 8, k) * st_Bf(t2 + 1, k);
    }
    bool bad = false;
    for (int i = 0; i < 4; i++) bad |= (fabsf(c[i] - ref[i]) > 1e-2f);
    if (bad) g_f1 = 0;
}

// ---------------------------------------------------------------------------
// 1) column bias
// ---------------------------------------------------------------------------
__global__ void bias_init_kernel(const float* __restrict__ mask)
{
    int i = blockIdx.x * blockDim.x + threadIdx.x;
    if (i < B_ * S_) g_colbias[i] = (1.0f - mask[i]) * -10000.0f;
}
__global__ void bias_scatter_kernel(const int* __restrict__ epos)
{
    int i = threadIdx.x;
    if (i < B_ * E_) atomicAdd(&g_colbias[(i / E_) * S_ + epos[i]], 1.0f);
}

// ---------------------------------------------------------------------------
// 2) fp32 -> bf16 hi/lo splits (mma path only)
// ---------------------------------------------------------------------------
__global__ void split_kernel(const float* __restrict__ src, bf16* __restrict__ hi,
                             bf16* __restrict__ lo, int n4)
{
    if (!g_f1) return;
    int i = blockIdx.x * blockDim.x + threadIdx.x;
    if (i >= n4) return;
    float4 v = reinterpret_cast<const float4*>(src)[i];
    float f[4] = {v.x, v.y, v.z, v.w};
    bf16 h[4], l[4];
#pragma unroll
    for (int j = 0; j < 4; j++) {
        h[j] = __float2bfloat16(f[j]);
        l[j] = __float2bfloat16(f[j] - __bfloat162float(h[j]));
    }
    reinterpret_cast<uint2*>(hi)[i] = *reinterpret_cast<uint2*>(h);
    reinterpret_cast<uint2*>(lo)[i] = *reinterpret_cast<uint2*>(l);
}

// ---------------------------------------------------------------------------
// MMA GEMM body (LDS fragment loads, no ldmatrix). C[128,128]/CTA, BK=32,
// 8 warps (2x4), warp tile 64x32, static 40KB smem, 3-term bf16 split.
//   EPI 0: bf16 hi/lo out (+ optional fp32 out) = acc + aux[col]
//   EPI 1: fp32 out = acc*alpha + aux[col]
//   EPI 2: fp32 out = acc
// ---------------------------------------------------------------------------
constexpr int RSB  = 80;              // 64 B data + 16 pad (16B-aligned, conflict-free)
constexpr int HALF = 128 * RSB;       // bytes per operand-half tile

template <int EPI>
__device__ __forceinline__
void mma_gemm_body(const bf16* __restrict__ Ahi, const bf16* __restrict__ Alo,
                   const bf16* __restrict__ Bhi, const bf16* __restrict__ Blo,
                   int K, int lda, int ldb,
                   float* __restrict__ Cf, bf16* __restrict__ Chi, bf16* __restrict__ Clo,
                   int ldc, const float* __restrict__ aux, float alpha)
{
    __shared__ __align__(128) char sm[4 * HALF];
    const int tid = threadIdx.x, lane = tid & 31, wid = tid >> 5;
    const int rowBase = blockIdx.y * 128, colBase = blockIdx.x * 128;
    const int wrow = (wid >> 2) * 64, wcol = (wid & 3) * 32;
    const int g = lane >> 2, t2b = (lane & 3) * 4;   // k-pair byte offset

    float acc[4][4][4];
#pragma unroll
    for (int a = 0; a < 4; a++)
#pragma unroll
        for (int b = 0; b < 4; b++)
#pragma unroll
            for (int c = 0; c < 4; c++) acc[a][b][c] = 0.f;

    const int C = K / 32;
    for (int i = 0; i < C; i++) {
        const int kc = i * 32;
        __syncthreads();
#pragma unroll
        for (int r = 0; r < 8; r++) {     // Ahi|Alo|Bhi|Blo 128x32 bf16 tiles
            const int half = r >> 1;
            const int rem = ((r & 1) << 8) | tid;
            const int row = rem >> 2, ch = rem & 3;
            const bf16* src = (half == 0) ? Ahi : (half == 1) ? Alo
                             : (half == 2) ? Bhi : Blo;
            const int base = (half < 2) ? rowBase : colBase;
            const int ld   = (half < 2) ? lda : ldb;
            const uint4 v = *reinterpret_cast<const uint4*>(
                src + (ll)(base + row) * ld + kc + ch * 8);
            *reinterpret_cast<uint4*>(sm + half * HALF + row * RSB + ch * 16) = v;
        }
        __syncthreads();

#pragma unroll
        for (int ks = 0; ks < 2; ks++) {
            const int kb = ks * 32;
            uint32_t af[4][4], bb[4][2], bl[4][2];
            // A-hi fragments (plain 4B shared loads; mma-layout addressing)
#pragma unroll
            for (int mt = 0; mt < 4; mt++) {
                const int r0 = (wrow + mt * 16 + g) * RSB + kb + t2b;
                af[mt][0] = *reinterpret_cast<const uint32_t*>(sm + r0);
                af[mt][1] = *reinterpret_cast<const uint32_t*>(sm + r0 + 8 * RSB);
                af[mt][2] = *reinterpret_cast<const uint32_t*>(sm + r0 + 16);
                af[mt][3] = *reinterpret_cast<const uint32_t*>(sm + r0 + 8 * RSB + 16);
            }
            // B-hi / B-lo fragments
#pragma unroll
            for (int nt = 0; nt < 4; nt++) {
                const int n0 = 2 * HALF + (wcol + nt * 8 + g) * RSB + kb + t2b;
                bb[nt][0] = *reinterpret_cast<const uint32_t*>(sm + n0);
                bb[nt][1] = *reinterpret_cast<const uint32_t*>(sm + n0 + 16);
                bl[nt][0] = *reinterpret_cast<const uint32_t*>(sm + n0 + HALF);
                bl[nt][1] = *reinterpret_cast<const uint32_t*>(sm + n0 + HALF + 16);
            }
            // hi*hi and hi*lo
#pragma unroll
            for (int mt = 0; mt < 4; mt++)
#pragma unroll
                for (int nt = 0; nt < 4; nt++) {
                    mma16816(acc[mt][nt], af[mt], bb[nt][0], bb[nt][1]);
                    mma16816(acc[mt][nt], af[mt], bl[nt][0], bl[nt][1]);
                }
            // A-lo fragments (reuse af), then lo*hi
#pragma unroll
            for (int mt = 0; mt < 4; mt++) {
                const int r0 = HALF + (wrow + mt * 16 + g) * RSB + kb + t2b;
                af[mt][0] = *reinterpret_cast<const uint32_t*>(sm + r0);
                af[mt][1] = *reinterpret_cast<const uint32_t*>(sm + r0 + 8 * RSB);
                af[mt][2] = *reinterpret_cast<const uint32_t*>(sm + r0 + 16);
                af[mt][3] = *reinterpret_cast<const uint32_t*>(sm + r0 + 8 * RSB + 16);
            }
#pragma unroll
            for (int mt = 0; mt < 4; mt++)
#pragma unroll
                for (int nt = 0; nt < 4; nt++)
                    mma16816(acc[mt][nt], af[mt], bb[nt][0], bb[nt][1]);
        }
    }

    // epilogue: frag rows (r0, r0+8), cols (c0, c0+1)
#pragma unroll
    for (int mt = 0; mt < 4; mt++) {
        const int r0 = rowBase + wrow + mt * 16 + (lane >> 2);
#pragma unroll
        for (int nt = 0; nt < 4; nt++) {
            const int c0 = colBase + wcol + nt * 8 + (lane & 3) * 2;
            const float* a4 = acc[mt][nt];
            if (EPI == 0) {
                const float bx = aux[c0], by = aux[c0 + 1];
                store_split(Chi, Clo, (ll)r0 * ldc + c0, a4[0] + bx, a4[1] + by);
                store_split(Chi, Clo, (ll)(r0 + 8) * ldc + c0, a4[2] + bx, a4[3] + by);
                if (Cf) {   // fp32 copy (V) for the SIMT fallback path
                    *reinterpret_cast<float2*>(Cf + (ll)r0 * ldc + c0) =
                        make_float2(a4[0] + bx, a4[1] + by);
                    *reinterpret_cast<float2*>(Cf + (ll)(r0 + 8) * ldc + c0) =
                        make_float2(a4[2] + bx, a4[3] + by);
                }
            } else if (EPI == 1) {
                const float bx = aux[c0], by = aux[c0 + 1];
                *reinterpret_cast<float2*>(Cf + (ll)r0 * ldc + c0) =
                    make_float2(a4[0] * alpha + bx, a4[1] * alpha + by);
                *reinterpret_cast<float2*>(Cf + (ll)(r0 + 8) * ldc + c0) =
                    make_float2(a4[2] * alpha + bx, a4[3] * alpha + by);
            } else {
                *reinterpret_cast<float2*>(Cf + (ll)r0 * ldc + c0) =
                    make_float2(a4[0], a4[1]);
                *reinterpret_cast<float2*>(Cf + (ll)(r0 + 8) * ldc + c0) =
                    make_float2(a4[2], a4[3]);
            }
        }
    }
}

template <int SEL>
__global__ __launch_bounds__(256)
void qkv_mma(const float* __restrict__ bias)
{
    if (!g_f1) return;
    const bf16* Wh = (SEL == 0) ? g_wqhi : (SEL == 1) ? g_wkhi : g_wvhi;
    const bf16* Wl = (SEL == 0) ? g_wqlo : (SEL == 1) ? g_wklo : g_wvlo;
    bf16* Oh = (SEL == 0) ? g_qhi : (SEL == 1) ? g_khi : g_vhi;
    bf16* Ol = (SEL == 0) ? g_qlo : (SEL == 1) ? g_klo : g_vlo;
    float* Of = (SEL == 2) ? g_v : nullptr;
    mma_gemm_body<0>(g_hshi, g_hslo, Wh, Wl, H_, H_, H_, Of, Oh, Ol, H_, bias, 1.0f);
}

__global__ __launch_bounds__(256)
void scores_mma(float alpha)
{
    if (!g_f1) return;
    const ll bz = blockIdx.z;
    mma_gemm_body<1>(g_qhi + bz * S_ * H_, g_qlo + bz * S_ * H_,
                     g_khi + bz * S_ * H_, g_klo + bz * S_ * H_,
                     H_, H_, H_,
                     g_scores + bz * S_ * S_, nullptr, nullptr, S_,
                     g_colbias + bz * S_, alpha);
}

__global__ __launch_bounds__(256)
void pv_mma(float* __restrict__ out)
{
    if (!g_f1) return;
    const ll bz = blockIdx.z;
    mma_gemm_body<2>(g_phi + bz * S_ * S_, g_plo + bz * S_ * S_,
                     g_vthi + bz * (ll)H_ * S_, g_vtlo + bz * (ll)H_ * S_,
                     S_, S_, S_,
                     out + bz * S_ * H_, nullptr, nullptr, H_, nullptr, 1.0f);
}

// ---------------------------------------------------------------------------
// Checkers (fp32 spot samples; any violation clears the flag)
// ---------------------------------------------------------------------------
__global__ void qkv_check(const float* __restrict__ hs,
                          const float* __restrict__ Wq, const float* __restrict__ bq,
                          const float* __restrict__ Wk, const float* __restrict__ bk,
                          const float* __restrict__ Wv, const float* __restrict__ bv)
{
    if (!g_f1) return;
    const int i = threadIdx.x;                     // 256 samples
    const ll pos = (ll)((i * 40503 + 17) % (B_ * S_));
    const int o  = (i * 257 + 31) % H_;
    float rq = bq[o], rk = bk[o], rv = bv[o];
    for (int h = 0; h < H_; h++) {
        const float x = hs[pos * H_ + h];
        rq += x * Wq[(ll)o * H_ + h];
        rk += x * Wk[(ll)o * H_ + h];
        rv += x * Wv[(ll)o * H_ + h];
    }
    const ll off = pos * H_ + o;
    const float gq = __bfloat162float(g_qhi[off]) + __bfloat162float(g_qlo[off]);
    const float gk = __bfloat162float(g_khi[off]) + __bfloat162float(g_klo[off]);
    const float gv = __bfloat162float(g_vhi[off]) + __bfloat162float(g_vlo[off]);
    const float gvf = g_v[off];
    bool bad = false;
    bad |= fabsf(gq - rq) > 0.02f + 0.01f * fabsf(rq);
    bad |= fabsf(gk - rk) > 0.02f + 0.01f * fabsf(rk);
    bad |= fabsf(gv - rv) > 0.02f + 0.01f * fabsf(rv);
    bad |= fabsf(gvf - rv) > 0.02f + 0.01f * fabsf(rv);
    if (bad) g_f1 = 0;
}

__global__ void scores_check(float alpha)
{
    if (!g_f1) return;
    const int i = threadIdx.x;                     // 256 samples
    const int b = i & 3;
    const int qp = (i * 811 + 5) % S_;
    const int kp = (i * 2731 + 9) % S_;
    const ll qo = ((ll)b * S_ + qp) * H_, ko = ((ll)b * S_ + kp) * H_;
    float dot = 0.f;
    for (int h = 0; h < H_; h++) {
        const float qv = __bfloat162float(g_qhi[qo + h]) + __bfloat162float(g_qlo[qo + h]);
        const float kv = __bfloat162float(g_khi[ko + h]) + __bfloat162float(g_klo[ko + h]);
        dot += qv * kv;
    }
    const float ref = dot * alpha + g_colbias[b * S_ + kp];
    const float got = g_scores[((ll)b * S_ + qp) * S_ + kp];
    if (fabsf(got - ref) > 0.05f + 0.02f * fabsf(ref)) g_f1 = 0;
}

__global__ void pv_check(const float* __restrict__ out)
{
    if (!g_f1) return;
    const int i = blockIdx.x * blockDim.x + threadIdx.x;   // 512 samples
    const int b = i & 3;
    const int s = (i * 1237 + 3) % S_;
    const int h = (i * 389 + 7) % H_;
    const ll po = ((ll)b * S_ + s) * S_;
    const ll vo = ((ll)b * H_ + h) * S_;
    float ref = 0.f;
    for (int k = 0; k < S_; k++) {
        const float p = __bfloat162float(g_phi[po + k]) + __bfloat162float(g_plo[po + k]);
        const float v = __bfloat162float(g_vthi[vo + k]) + __bfloat162float(g_vtlo[vo + k]);
        ref += p * v;
    }
    const float got = out[((ll)b * S_ + s) * H_ + h];
    if (fabsf(got - ref) > 0.02f + 0.01f * fabsf(ref)) g_f2 = 0;
}

// ---------------------------------------------------------------------------
// V transpose (mma path): V[b][s][h] hi/lo -> Vt[b][h][s] hi/lo
// ---------------------------------------------------------------------------
__global__ void vtrans_kernel()
{
    if (!g_f1) return;
    const int b = blockIdx.z >> 1;
    const bool lo = blockIdx.z & 1;
    const bf16* src = (lo ? g_vlo : g_vhi) + (ll)b * S_ * H_;
    bf16* dst = (lo ? g_vtlo : g_vthi) + (ll)b * H_ * S_;
    __shared__ bf16 tile[32][33];
    const int h0 = blockIdx.x * 32, s0 = blockIdx.y * 32;
    const int tx = threadIdx.x, ty = threadIdx.y;
#pragma unroll
    for (int j = ty; j < 32; j += 8) tile[j][tx] = src[(ll)(s0 + j) * H_ + h0 + tx];
    __syncthreads();
#pragma unroll
    for (int j = ty; j < 32; j += 8) dst[(ll)(h0 + j) * S_ + s0 + tx] = tile[tx][j];
}

// ---------------------------------------------------------------------------
// SIMT fp32 SGEMM (verbatim from the R4-passing kernel)
// ---------------------------------------------------------------------------
constexpr int BM = 128, BN = 128, BKs = 8, TM = 8, TN = 8, PAD = 4;

template <bool BT, int EPI>
__device__ __forceinline__
void sgemm_body(const float* __restrict__ A, const float* __restrict__ Bm,
                float* __restrict__ C,
                int K, int lda, int ldb, int ldc,
                const float* __restrict__ auxp, float alpha)
{
    __shared__ float As[2][BKs][BM + PAD];
    __shared__ float Bs[2][BKs][BN + PAD];

    const int tid = threadIdx.x;
    const int tx = tid & 15;
    const int ty = tid >> 4;
    const int rowBase = blockIdx.y * BM;
    const int colBase = blockIdx.x * BN;

    const int arow = tid >> 1;
    const int acol = (tid & 1) * 4;
    int brow, bcol;
    if (BT) { brow = tid >> 1; bcol = (tid & 1) * 4; }
    else    { brow = tid >> 5; bcol = (tid & 31) * 4; }

    const float* Aptr = A + (ll)(rowBase + arow) * lda + acol;
    const float* Bptr = BT ? (Bm + (ll)(colBase + brow) * ldb + bcol)
                           : (Bm + (ll)brow * ldb + colBase + bcol);

    float acc[TM][TN] = {};

    float4 av = *reinterpret_cast<const float4*>(Aptr);
    float4 bv = *reinterpret_cast<const float4*>(Bptr);
    As[0][acol + 0][arow] = av.x; As[0][acol + 1][arow] = av.y;
    As[0][acol + 2][arow] = av.z; As[0][acol + 3][arow] = av.w;
    if (BT) {
        Bs[0][bcol + 0][brow] = bv.x; Bs[0][bcol + 1][brow] = bv.y;
        Bs[0][bcol + 2][brow] = bv.z; Bs[0][bcol + 3][brow] = bv.w;
    } else {
        *reinterpret_cast<float4*>(&Bs[0][brow][bcol]) = bv;
    }
    __syncthreads();

    int buf = 0;
    for (int kt = 0; kt < K; kt += BKs) {
        const bool more = (kt + BKs) < K;
        if (more) {
            av = *reinterpret_cast<const float4*>(Aptr + kt + BKs);
            if (BT) bv = *reinterpret_cast<const float4*>(Bptr + kt + BKs);
            else    bv = *reinterpret_cast<const float4*>(Bptr + (ll)(kt + BKs) * ldb);
        }
#pragma unroll
        for (int kk = 0; kk < BKs; kk++) {
            float4 a0 = *reinterpret_cast<const float4*>(&As[buf][kk][ty * TM]);
            float4 a1 = *reinterpret_cast<const float4*>(&As[buf][kk][ty * TM + 4]);
            float4 b0 = *reinterpret_cast<const float4*>(&Bs[buf][kk][tx * TN]);
            float4 b1 = *reinterpret_cast<const float4*>(&Bs[buf][kk][tx * TN + 4]);
            float af[TM] = {a0.x, a0.y, a0.z, a0.w, a1.x, a1.y, a1.z, a1.w};
            float bf[TN] = {b0.x, b0.y, b0.z, b0.w, b1.x, b1.y, b1.z, b1.w};
#pragma unroll
            for (int i = 0; i < TM; i++)
#pragma unroll
                for (int j = 0; j < TN; j++)
                    acc[i][j] = fmaf(af[i], bf[j], acc[i][j]);
        }
        if (more) {
            const int nb = buf ^ 1;
            As[nb][acol + 0][arow] = av.x; As[nb][acol + 1][arow] = av.y;
            As[nb][acol + 2][arow] = av.z; As[nb][acol + 3][arow] = av.w;
            if (BT) {
                Bs[nb][bcol + 0][brow] = bv.x; Bs[nb][bcol + 1][brow] = bv.y;
                Bs[nb][bcol + 2][brow] = bv.z; Bs[nb][bcol + 3][brow] = bv.w;
            } else {
                *reinterpret_cast<float4*>(&Bs[nb][brow][bcol]) = bv;
            }
        }
        __syncthreads();
        buf ^= 1;
    }

    float auxv[TN];
    if (EPI < 2) {
#pragma unroll
        for (int j = 0; j < TN; j++) auxv[j] = auxp[colBase + tx * TN + j];
    }
#pragma unroll
    for (int i = 0; i < TM; i++) {
        float* cp = C + (ll)(rowBase + ty * TM + i) * ldc + colBase + tx * TN;
        float o[TN];
#pragma unroll
        for (int j = 0; j < TN; j++) {
            float vv = acc[i][j];
            if (EPI == 0)      vv = vv + auxv[j];
            else if (EPI == 1) vv = vv * alpha + auxv[j];
            o[j] = vv;
        }
        *reinterpret_cast<float4*>(cp)     = make_float4(o[0], o[1], o[2], o[3]);
        *reinterpret_cast<float4*>(cp + 4) = make_float4(o[4], o[5], o[6], o[7]);
    }
}

template <int SEL>
__global__ __launch_bounds__(256)
void qkv_simt(const float* __restrict__ hs, const float* __restrict__ W,
              const float* __restrict__ bias)
{
    if (g_f1) return;
    float* out = (SEL == 0) ? g_q : (SEL == 1) ? g_k : g_v;
    sgemm_body<true, 0>(hs, W, out, H_, H_, H_, H_, bias, 1.0f);
}

__global__ __launch_bounds__(256)
void scores_simt(float alpha)
{
    if (g_f1) return;
    const int bz = blockIdx.z;
    sgemm_body<true, 1>(g_q + (ll)bz * S_ * H_, g_k + (ll)bz * S_ * H_,
                        g_scores + (ll)bz * S_ * S_,
                        H_, H_, H_, S_, g_colbias + bz * S_, alpha);
}

__global__ __launch_bounds__(256)
void pv_simt(float* __restrict__ out)
{
    if (g_f1 && g_f2) return;   // run if any fallback engaged
    const int bz = blockIdx.z;
    sgemm_body<false, 2>(g_scores + (ll)bz * S_ * S_, g_v + (ll)bz * S_ * H_,
                         out + (ll)bz * S_ * H_,
                         S_, S_, H_, H_, nullptr, 1.0f);
}

// ---------------------------------------------------------------------------
// Softmax: fp32 in -> (f1 ? bf16 hi/lo probs : fp32 in-place). g_scores kept
// intact in mma mode so the PV rescue path can re-softmax it.
// ---------------------------------------------------------------------------
__device__ __forceinline__ void softmax_core(float4* v, float& inv, int t, int lane, int w)
{
    __shared__ float sh[8];
    __shared__ float bres;
    float m = -1e30f;
#pragma unroll
    for (int i = 0; i < 4; i++)
        m = fmaxf(m, fmaxf(fmaxf(v[i].x, v[i].y), fmaxf(v[i].z, v[i].w)));
#pragma unroll
    for (int o = 16; o; o >>= 1) m = fmaxf(m, __shfl_xor_sync(0xffffffffu, m, o));
    if (!lane) sh[w] = m;
    __syncthreads();
    if (t == 0) {
        float mm = sh[0];
#pragma unroll
        for (int i = 1; i < 8; i++) mm = fmaxf(mm, sh[i]);
        bres = mm;
    }
    __syncthreads();
    m = bres;
    float s = 0.f;
#pragma unroll
    for (int i = 0; i < 4; i++) {
        v[i].x = __expf(v[i].x - m); v[i].y = __expf(v[i].y - m);
        v[i].z = __expf(v[i].z - m); v[i].w = __expf(v[i].w - m);
        s += (v[i].x + v[i].y) + (v[i].z + v[i].w);
    }
#pragma unroll
    for (int o = 16; o; o >>= 1) s += __shfl_xor_sync(0xffffffffu, s, o);
    if (!lane) sh[w] = s;
    __syncthreads();
    if (t == 0) {
        float ss = 0.f;
#pragma unroll
        for (int i = 0; i < 8; i++) ss += sh[i];
        bres = ss;
    }
    __syncthreads();
    inv = 1.0f / bres;
}

__global__ __launch_bounds__(256) void softmax_main()
{
    const ll row = blockIdx.x;
    float4* p4 = reinterpret_cast<float4*>(g_scores + row * (ll)S_);
    const int t = threadIdx.x, lane = t & 31, w = t >> 5;
    float4 v[4];
#pragma unroll
    for (int i = 0; i < 4; i++) v[i] = p4[t + i * 256];
    float inv;
    softmax_core(v, inv, t, lane, w);
    if (g_f1) {
        uint2* ph = reinterpret_cast<uint2*>(g_phi + row * (ll)S_);
        uint2* pl = reinterpret_cast<uint2*>(g_plo + row * (ll)S_);
#pragma unroll
        for (int i = 0; i < 4; i++) {
            float f[4] = {v[i].x * inv, v[i].y * inv, v[i].z * inv, v[i].w * inv};
            bf16 h[4], l[4];
#pragma unroll
            for (int j = 0; j < 4; j++) {
                h[j] = __float2bfloat16(f[j]);
                l[j] = __float2bfloat16(f[j] - __bfloat162float(h[j]));
            }
            ph[t + i * 256] = *reinterpret_cast<uint2*>(h);
            pl[t + i * 256] = *reinterpret_cast<uint2*>(l);
        }
    } else {
#pragma unroll
        for (int i = 0; i < 4; i++) {
            v[i].x *= inv; v[i].y *= inv; v[i].z *= inv; v[i].w *= inv;
            p4[t + i * 256] = v[i];
        }
    }
}

// PV rescue: mma pipeline was OK through scores but PV failed => produce fp32
// probabilities in-place so pv_simt can run from g_scores + g_v.
__global__ __launch_bounds__(256) void softmax_rescue()
{
    if (!(g_f1 && !g_f2)) return;
    const ll row = blockIdx.x;
    float4* p4 = reinterpret_cast<float4*>(g_scores + row * (ll)S_);
    const int t = threadIdx.x, lane = t & 31, w = t >> 5;
    float4 v[4];
#pragma unroll
    for (int i = 0; i < 4; i++) v[i] = p4[t + i * 256];
    float inv;
    softmax_core(v, inv, t, lane, w);
#pragma unroll
    for (int i = 0; i < 4; i++) {
        v[i].x *= inv; v[i].y *= inv; v[i].z *= inv; v[i].w *= inv;
        p4[t + i * 256] = v[i];
    }
}

// ---------------------------------------------------------------------------
extern "C" void kernel_launch(void* const* d_in, const int* in_sizes, int n_in,
                              void* d_out, int out_size)
{
    const float* hs   = (const float*)d_in[0];
    const float* mask = (const float*)d_in[1];
    const int*   epos = (const int*)d_in[2];
    const float* Wq   = (const float*)d_in[3];
    const float* bq   = (const float*)d_in[4];
    const float* Wk   = (const float*)d_in[5];
    const float* bk   = (const float*)d_in[6];
    const float* Wv   = (const float*)d_in[7];
    const float* bv   = (const float*)d_in[8];
    float* out = (float*)d_out;

    // 0) flags + mma self-test
    flag_init_kernel<<<1, 1>>>();
    selftest_mma<<<1, 32>>>();

    // 1) column bias (both paths)
    bias_init_kernel<<<(B_ * S_ + 255) / 256, 256>>>(mask);
    bias_scatter_kernel<<<1, 256>>>(epos);

    // 2) splits (mma path, gated)
    {
        const int n4 = B_ * S_ * H_ / 4;
        split_kernel<<<(n4 + 255) / 256, 256>>>(hs, g_hshi, g_hslo, n4);
        const int w4 = H_ * H_ / 4;
        split_kernel<<<(w4 + 255) / 256, 256>>>(Wq, g_wqhi, g_wqlo, w4);
        split_kernel<<<(w4 + 255) / 256, 256>>>(Wk, g_wkhi, g_wklo, w4);
        split_kernel<<<(w4 + 255) / 256, 256>>>(Wv, g_wvhi, g_wvlo, w4);
    }

    const dim3 gQKV(H_ / 128, (B_ * S_) / 128, 1);
    const dim3 gSC(S_ / 128, S_ / 128, B_);
    const dim3 gPV(H_ / 128, S_ / 128, B_);
    const float alpha = 1.0f / sqrtf((float)H_);

    // 3) mma pipeline with checks (all gated on f1)
    qkv_mma<0><<<gQKV, 256>>>(bq);
    qkv_mma<1><<<gQKV, 256>>>(bk);
    qkv_mma<2><<<gQKV, 256>>>(bv);
    qkv_check<<<1, 256>>>(hs, Wq, bq, Wk, bk, Wv, bv);
    vtrans_kernel<<<dim3(H_ / 32, S_ / 32, B_ * 2), dim3(32, 8)>>>();
    scores_mma<<<gSC, 256>>>(alpha);
    scores_check<<<1, 256>>>(alpha);

    // 4) SIMT fallback stages (gated on !f1; f1 final after scores_check)
    qkv_simt<0><<<gQKV, 256>>>(hs, Wq, bq);
    qkv_simt<1><<<gQKV, 256>>>(hs, Wk, bk);
    qkv_simt<2><<<gQKV, 256>>>(hs, Wv, bv);
    scores_simt<<<gSC, 256>>>(alpha);

    // 5) softmax (mode by f1)
    softmax_main<<<B_ * S_, 256>>>();

    // 6) PV: mma + check + rescue fallback
    pv_mma<<<gPV, 256>>>(out);
    pv_check<<<2, 256>>>(out);
    softmax_rescue<<<B_ * S_, 256>>>();
    pv_simt<<<gPV, 256>>>(out);
}

// round 13
// speedup vs baseline: 1.3836x; 1.3836x over previous
#include <cuda_runtime.h>
#include <math.h>

// Problem shape (fixed by setup_inputs)
#define B_ 4
#define S_ 4096
#define H_ 768
#define E_ 64

typedef long long ll;

// ---------------------------------------------------------------------------
// Scratch (allocation-free per harness rules)
// ---------------------------------------------------------------------------
__device__ __align__(256) float g_q[(size_t)B_ * S_ * H_];
__device__ __align__(256) float g_k[(size_t)B_ * S_ * H_];
__device__ __align__(256) float g_v[(size_t)B_ * S_ * H_];
__device__ __align__(256) float g_scores[(size_t)B_ * S_ * S_];   // 256 MB
__device__ __align__(256) float g_colbias[B_ * S_];

// ---------------------------------------------------------------------------
// Column-bias prep: colbias[b][s] = (1-mask)*-10000 + (#entity hits at s)
// ---------------------------------------------------------------------------
__global__ void bias_init_kernel(const float* __restrict__ mask)
{
    int i = blockIdx.x * blockDim.x + threadIdx.x;
    if (i < B_ * S_) g_colbias[i] = (1.0f - mask[i]) * -10000.0f;
}
__global__ void bias_scatter_kernel(const int* __restrict__ epos)
{
    int i = threadIdx.x;
    if (i < B_ * E_) atomicAdd(&g_colbias[(i / E_) * S_ + epos[i]], 1.0f);
}

// ---------------------------------------------------------------------------
// Tiled SGEMM: C = A * op(B), 128x128 block, 8x8/thread, BK=8, double-buffered.
//   BT=true : B is N x K row-major (NT gemm)   -- QKV, scores
//   BT=false: B is K x N row-major (NN gemm)   -- P @ V
//   EPI=0: C = acc + aux[col]; EPI=1: C = acc*alpha + aux[col]; EPI=2: C = acc
// Bs uses a group-padded layout col' = col + (col>>3)*4 (row length 196) so the
// 8-float-stride float4 fragment reads hit distinct banks (R4 had 2-way
// conflicts there). As reads are warp-broadcast => left unpadded.
// ---------------------------------------------------------------------------
constexpr int BM = 128, BN = 128, BK = 8, TM = 8, TN = 8, PAD = 4;
constexpr int BNP = 196;   // 16 groups * (8 data + 4 pad) + 4

__device__ __forceinline__ int bmap(int c) { return c + ((c >> 3) << 2); }

template <bool BT, int EPI>
__device__ __forceinline__
void sgemm_body(const float* __restrict__ A, const float* __restrict__ Bm,
                float* __restrict__ C,
                int K, int lda, int ldb, int ldc,
                const float* __restrict__ auxp, float alpha)
{
    __shared__ float As[2][BK][BM + PAD];
    __shared__ float Bs[2][BK][BNP];

    const int tid = threadIdx.x;
    const int tx = tid & 15;
    const int ty = tid >> 4;
    const int rowBase = blockIdx.y * BM;
    const int colBase = blockIdx.x * BN;

    // load mapping: 256 threads, 128x8 tile => one float4 per thread
    const int arow = tid >> 1;
    const int acol = (tid & 1) * 4;
    int brow, bcol;
    if (BT) { brow = tid >> 1; bcol = (tid & 1) * 4; }    // brow = n, bcol = k
    else    { brow = tid >> 5; bcol = (tid & 31) * 4; }   // brow = k, bcol = n

    const float* Aptr = A + (ll)(rowBase + arow) * lda + acol;
    const float* Bptr = BT ? (Bm + (ll)(colBase + brow) * ldb + bcol)
                           : (Bm + (ll)brow * ldb + colBase + bcol);

    float acc[TM][TN] = {};

    float4 av = *reinterpret_cast<const float4*>(Aptr);
    float4 bv = *reinterpret_cast<const float4*>(Bptr);
    As[0][acol + 0][arow] = av.x; As[0][acol + 1][arow] = av.y;
    As[0][acol + 2][arow] = av.z; As[0][acol + 3][arow] = av.w;
    if (BT) {
        const int bn = bmap(brow);
        Bs[0][bcol + 0][bn] = bv.x; Bs[0][bcol + 1][bn] = bv.y;
        Bs[0][bcol + 2][bn] = bv.z; Bs[0][bcol + 3][bn] = bv.w;
    } else {
        *reinterpret_cast<float4*>(&Bs[0][brow][bmap(bcol)]) = bv;
    }
    __syncthreads();

    int buf = 0;
    for (int kt = 0; kt < K; kt += BK) {
        const bool more = (kt + BK) < K;
        if (more) {
            av = *reinterpret_cast<const float4*>(Aptr + kt + BK);
            if (BT) bv = *reinterpret_cast<const float4*>(Bptr + kt + BK);
            else    bv = *reinterpret_cast<const float4*>(Bptr + (ll)(kt + BK) * ldb);
        }
#pragma unroll
        for (int kk = 0; kk < BK; kk++) {
            float4 a0 = *reinterpret_cast<const float4*>(&As[buf][kk][ty * TM]);
            float4 a1 = *reinterpret_cast<const float4*>(&As[buf][kk][ty * TM + 4]);
            float4 b0 = *reinterpret_cast<const float4*>(&Bs[buf][kk][tx * TN + tx * 4]);
            float4 b1 = *reinterpret_cast<const float4*>(&Bs[buf][kk][tx * TN + tx * 4 + 4]);
            float af[TM] = {a0.x, a0.y, a0.z, a0.w, a1.x, a1.y, a1.z, a1.w};
            float bf[TN] = {b0.x, b0.y, b0.z, b0.w, b1.x, b1.y, b1.z, b1.w};
#pragma unroll
            for (int i = 0; i < TM; i++)
#pragma unroll
                for (int j = 0; j < TN; j++)
                    acc[i][j] = fmaf(af[i], bf[j], acc[i][j]);
        }
        if (more) {
            const int nb = buf ^ 1;
            As[nb][acol + 0][arow] = av.x; As[nb][acol + 1][arow] = av.y;
            As[nb][acol + 2][arow] = av.z; As[nb][acol + 3][arow] = av.w;
            if (BT) {
                const int bn = bmap(brow);
                Bs[nb][bcol + 0][bn] = bv.x; Bs[nb][bcol + 1][bn] = bv.y;
                Bs[nb][bcol + 2][bn] = bv.z; Bs[nb][bcol + 3][bn] = bv.w;
            } else {
                *reinterpret_cast<float4*>(&Bs[nb][brow][bmap(bcol)]) = bv;
            }
        }
        __syncthreads();
        buf ^= 1;
    }

    float auxv[TN];
    if (EPI < 2) {
#pragma unroll
        for (int j = 0; j < TN; j++) auxv[j] = auxp[colBase + tx * TN + j];
    }
#pragma unroll
    for (int i = 0; i < TM; i++) {
        float* cp = C + (ll)(rowBase + ty * TM + i) * ldc + colBase + tx * TN;
        float o[TN];
#pragma unroll
        for (int j = 0; j < TN; j++) {
            float vv = acc[i][j];
            if (EPI == 0)      vv = vv + auxv[j];
            else if (EPI == 1) vv = vv * alpha + auxv[j];
            o[j] = vv;
        }
        *reinterpret_cast<float4*>(cp)     = make_float4(o[0], o[1], o[2], o[3]);
        *reinterpret_cast<float4*>(cp + 4) = make_float4(o[4], o[5], o[6], o[7]);
    }
}

// ---- wrappers ---------------------------------------------------------------
// Fused QKV: one launch, blockIdx.z selects {Q,K,V} (saves 2 kernel tails).
__global__ __launch_bounds__(256)
void qkv_kernel(const float* __restrict__ hs,
                const float* __restrict__ Wq, const float* __restrict__ bq,
                const float* __restrict__ Wk, const float* __restrict__ bk,
                const float* __restrict__ Wv, const float* __restrict__ bv)
{
    const int z = blockIdx.z;
    const float* W    = (z == 0) ? Wq : (z == 1) ? Wk : Wv;
    const float* bias = (z == 0) ? bq : (z == 1) ? bk : bv;
    float* out        = (z == 0) ? g_q : (z == 1) ? g_k : g_v;
    sgemm_body<true, 0>(hs, W, out, H_, H_, H_, H_, bias, 1.0f);
}

__global__ __launch_bounds__(256)
void scores_kernel(float alpha)
{
    const int bz = blockIdx.z;
    sgemm_body<true, 1>(g_q + (ll)bz * S_ * H_, g_k + (ll)bz * S_ * H_,
                        g_scores + (ll)bz * S_ * S_,
                        H_, H_, H_, S_, g_colbias + bz * S_, alpha);
}

__global__ __launch_bounds__(256)
void pv_kernel(float* __restrict__ out)
{
    const int bz = blockIdx.z;
    sgemm_body<false, 2>(g_scores + (ll)bz * S_ * S_, g_v + (ll)bz * S_ * H_,
                         out + (ll)bz * S_ * H_,
                         S_, S_, H_, H_, nullptr, 1.0f);
}

// ---------------------------------------------------------------------------
// Row softmax over S_=4096 columns. One block per row, values in registers:
// exactly one read + one write of the 256 MB scores buffer.
// ---------------------------------------------------------------------------
__global__ __launch_bounds__(256) void softmax_rows()
{
    const ll row = blockIdx.x;
    float4* p4 = reinterpret_cast<float4*>(g_scores + row * (ll)S_);
    const int t = threadIdx.x;
    const int lane = t & 31, w = t >> 5;

    float4 v[4];
    float m = -1e30f;
#pragma unroll
    for (int i = 0; i < 4; i++) {
        v[i] = p4[t + i * 256];
        m = fmaxf(m, fmaxf(fmaxf(v[i].x, v[i].y), fmaxf(v[i].z, v[i].w)));
    }

    __shared__ float sh[8];
    __shared__ float bres;
#pragma unroll
    for (int o = 16; o; o >>= 1) m = fmaxf(m, __shfl_xor_sync(0xffffffffu, m, o));
    if (!lane) sh[w] = m;
    __syncthreads();
    if (t == 0) {
        float mm = sh[0];
#pragma unroll
        for (int i = 1; i < 8; i++) mm = fmaxf(mm, sh[i]);
        bres = mm;
    }
    __syncthreads();
    m = bres;

    float s = 0.f;
#pragma unroll
    for (int i = 0; i < 4; i++) {
        v[i].x = __expf(v[i].x - m); v[i].y = __expf(v[i].y - m);
        v[i].z = __expf(v[i].z - m); v[i].w = __expf(v[i].w - m);
        s += (v[i].x + v[i].y) + (v[i].z + v[i].w);
    }
#pragma unroll
    for (int o = 16; o; o >>= 1) s += __shfl_xor_sync(0xffffffffu, s, o);
    if (!lane) sh[w] = s;
    __syncthreads();
    if (t == 0) {
        float ss = 0.f;
#pragma unroll
        for (int i = 0; i < 8; i++) ss += sh[i];
        bres = ss;
    }
    __syncthreads();
    const float inv = 1.0f / bres;
#pragma unroll
    for (int i = 0; i < 4; i++) {
        v[i].x *= inv; v[i].y *= inv; v[i].z *= inv; v[i].w *= inv;
        p4[t + i * 256] = v[i];
    }
}

// ---------------------------------------------------------------------------
extern "C" void kernel_launch(void* const* d_in, const int* in_sizes, int n_in,
                              void* d_out, int out_size)
{
    const float* hs   = (const float*)d_in[0];
    const float* mask = (const float*)d_in[1];
    const int*   epos = (const int*)d_in[2];
    const float* Wq   = (const float*)d_in[3];
    const float* bq   = (const float*)d_in[4];
    const float* Wk   = (const float*)d_in[5];
    const float* bk   = (const float*)d_in[6];
    const float* Wv   = (const float*)d_in[7];
    const float* bv   = (const float*)d_in[8];
    float* out = (float*)d_out;

    // 1) column bias (mask fold + entity scatter)
    bias_init_kernel<<<(B_ * S_ + 255) / 256, 256>>>(mask);
    bias_scatter_kernel<<<1, 256>>>(epos);

    // 2) QKV projections (fused NT gemm, bias epilogue)
    qkv_kernel<<<dim3(H_ / BN, (B_ * S_) / BM, 3), 256>>>(hs, Wq, bq, Wk, bk, Wv, bv);

    // 3) scores = (Q Kt)/sqrt(H) + colbias   (batched NT gemm)
    const float alpha = 1.0f / sqrtf((float)H_);
    scores_kernel<<<dim3(S_ / BN, S_ / BM, B_), 256>>>(alpha);

    // 4) row softmax (in-place fp32)
    softmax_rows<<<B_ * S_, 256>>>();

    // 5) context = P V   (batched NN gemm) -> d_out
    pv_kernel<<<dim3(H_ / BN, S_ / BM, B_), 256>>>(out);
}

// round 14
// speedup vs baseline: 1.5987x; 1.1555x over previous
#include <cuda_runtime.h>
#include <math.h>

// Problem shape (fixed by setup_inputs)
#define B_ 4
#define S_ 4096
#define H_ 768
#define E_ 64

typedef long long ll;
typedef unsigned long long ull;

// ---------------------------------------------------------------------------
// Scratch (allocation-free per harness rules)
// ---------------------------------------------------------------------------
__device__ __align__(256) float g_q[(size_t)B_ * S_ * H_];
__device__ __align__(256) float g_k[(size_t)B_ * S_ * H_];
__device__ __align__(256) float g_v[(size_t)B_ * S_ * H_];
__device__ __align__(256) float g_scores[(size_t)B_ * S_ * S_];   // 256 MB
__device__ __align__(256) float g_colbias[B_ * S_];
__device__ int g_useF2;   // HW-behavior-derived => deterministic across replays

// ---------------------------------------------------------------------------
// Packed fp32x2 helpers (Blackwell FFMA2; PTX-only pattern)
// ---------------------------------------------------------------------------
__device__ __forceinline__ ull bcast2(float x) {
    ull r;
    asm("mov.b64 %0, {%1, %1};" : "=l"(r) : "f"(x));
    return r;
}
__device__ __forceinline__ void fma2(ull& c, ull a, ull b) {
    asm("fma.rn.f32x2 %0, %1, %2, %0;" : "+l"(c) : "l"(a), "l"(b));
}

__global__ void selftest_f32x2()
{
    if (threadIdx.x != 0) return;
    ull a2, b2, c2;
    asm("mov.b64 %0, {%1, %2};" : "=l"(a2) : "f"(2.0f), "f"(3.0f));
    asm("mov.b64 %0, {%1, %2};" : "=l"(b2) : "f"(5.0f), "f"(7.0f));
    asm("mov.b64 %0, {%1, %2};" : "=l"(c2) : "f"(1.0f), "f"(1.0f));
    fma2(c2, a2, b2);   // expect (11, 22)
    const float lo = __uint_as_float((unsigned)c2);
    const float hi = __uint_as_float((unsigned)(c2 >> 32));
    g_useF2 = (fabsf(lo - 11.0f) < 1e-3f && fabsf(hi - 22.0f) < 1e-3f) ? 1 : 0;
}

// ---------------------------------------------------------------------------
// Column-bias prep: colbias[b][s] = (1-mask)*-10000 + (#entity hits at s)
// ---------------------------------------------------------------------------
__global__ void bias_init_kernel(const float* __restrict__ mask)
{
    int i = blockIdx.x * blockDim.x + threadIdx.x;
    if (i < B_ * S_) g_colbias[i] = (1.0f - mask[i]) * -10000.0f;
}
__global__ void bias_scatter_kernel(const int* __restrict__ epos)
{
    int i = threadIdx.x;
    if (i < B_ * E_) atomicAdd(&g_colbias[(i / E_) * S_ + epos[i]], 1.0f);
}

// ---------------------------------------------------------------------------
// Tiled SGEMM: C = A * op(B), 128x128 block, 8x8/thread, BK=8, double-buffered.
//   BT : B is NxK (NT) vs KxN (NN) row-major.
//   EPI=0: C=acc+aux[col]; EPI=1: C=acc*alpha+aux[col]; EPI=2: C=acc
//   F2 : inner product via packed fma.rn.f32x2 (exact same per-lane IEEE fp32)
// Bs group-padded (col' = col + (col>>3)*4, row len 196) => conflict-free reads.
// ---------------------------------------------------------------------------
constexpr int BM = 128, BN = 128, BK = 8, TM = 8, TN = 8, PAD = 4;
constexpr int BNP = 196;

__device__ __forceinline__ int bmap(int c) { return c + ((c >> 3) << 2); }

template <bool BT, int EPI, bool F2>
__device__ __forceinline__
void sgemm_body(const float* __restrict__ A, const float* __restrict__ Bm,
                float* __restrict__ C,
                int K, int lda, int ldb, int ldc,
                const float* __restrict__ auxp, float alpha)
{
    __shared__ float As[2][BK][BM + PAD];
    __shared__ float Bs[2][BK][BNP];

    const int tid = threadIdx.x;
    const int tx = tid & 15;
    const int ty = tid >> 4;
    const int rowBase = blockIdx.y * BM;
    const int colBase = blockIdx.x * BN;

    const int arow = tid >> 1;
    const int acol = (tid & 1) * 4;
    int brow, bcol;
    if (BT) { brow = tid >> 1; bcol = (tid & 1) * 4; }
    else    { brow = tid >> 5; bcol = (tid & 31) * 4; }

    const float* Aptr = A + (ll)(rowBase + arow) * lda + acol;
    const float* Bptr = BT ? (Bm + (ll)(colBase + brow) * ldb + bcol)
                           : (Bm + (ll)brow * ldb + colBase + bcol);

    // accumulators: packed pairs along j (F2) or scalar grid (!F2)
    ull   acc2[TM][TN / 2];
    float accs[TM][TN];
    if (F2) {
#pragma unroll
        for (int i = 0; i < TM; i++)
#pragma unroll
            for (int j = 0; j < TN / 2; j++) acc2[i][j] = 0ull;
    } else {
#pragma unroll
        for (int i = 0; i < TM; i++)
#pragma unroll
            for (int j = 0; j < TN; j++) accs[i][j] = 0.f;
    }

    float4 av = *reinterpret_cast<const float4*>(Aptr);
    float4 bv = *reinterpret_cast<const float4*>(Bptr);
    As[0][acol + 0][arow] = av.x; As[0][acol + 1][arow] = av.y;
    As[0][acol + 2][arow] = av.z; As[0][acol + 3][arow] = av.w;
    if (BT) {
        const int bn = bmap(brow);
        Bs[0][bcol + 0][bn] = bv.x; Bs[0][bcol + 1][bn] = bv.y;
        Bs[0][bcol + 2][bn] = bv.z; Bs[0][bcol + 3][bn] = bv.w;
    } else {
        *reinterpret_cast<float4*>(&Bs[0][brow][bmap(bcol)]) = bv;
    }
    __syncthreads();

    int buf = 0;
    for (int kt = 0; kt < K; kt += BK) {
        const bool more = (kt + BK) < K;
        if (more) {
            av = *reinterpret_cast<const float4*>(Aptr + kt + BK);
            if (BT) bv = *reinterpret_cast<const float4*>(Bptr + kt + BK);
            else    bv = *reinterpret_cast<const float4*>(Bptr + (ll)(kt + BK) * ldb);
        }
#pragma unroll
        for (int kk = 0; kk < BK; kk++) {
            float4 a0 = *reinterpret_cast<const float4*>(&As[buf][kk][ty * TM]);
            float4 a1 = *reinterpret_cast<const float4*>(&As[buf][kk][ty * TM + 4]);
            float af[TM] = {a0.x, a0.y, a0.z, a0.w, a1.x, a1.y, a1.z, a1.w};
            if (F2) {
                const ulonglong2* bp = reinterpret_cast<const ulonglong2*>(
                    &Bs[buf][kk][tx * TN + tx * 4]);
                const ulonglong2 u0 = bp[0];
                const ulonglong2 u1 = bp[1];
                ull b2[4] = {u0.x, u0.y, u1.x, u1.y};
#pragma unroll
                for (int i = 0; i < TM; i++) {
                    const ull a2 = bcast2(af[i]);
#pragma unroll
                    for (int j = 0; j < TN / 2; j++) fma2(acc2[i][j], a2, b2[j]);
                }
            } else {
                float4 b0 = *reinterpret_cast<const float4*>(&Bs[buf][kk][tx * TN + tx * 4]);
                float4 b1 = *reinterpret_cast<const float4*>(&Bs[buf][kk][tx * TN + tx * 4 + 4]);
                float bf[TN] = {b0.x, b0.y, b0.z, b0.w, b1.x, b1.y, b1.z, b1.w};
#pragma unroll
                for (int i = 0; i < TM; i++)
#pragma unroll
                    for (int j = 0; j < TN; j++)
                        accs[i][j] = fmaf(af[i], bf[j], accs[i][j]);
            }
        }
        if (more) {
            const int nb = buf ^ 1;
            As[nb][acol + 0][arow] = av.x; As[nb][acol + 1][arow] = av.y;
            As[nb][acol + 2][arow] = av.z; As[nb][acol + 3][arow] = av.w;
            if (BT) {
                const int bn = bmap(brow);
                Bs[nb][bcol + 0][bn] = bv.x; Bs[nb][bcol + 1][bn] = bv.y;
                Bs[nb][bcol + 2][bn] = bv.z; Bs[nb][bcol + 3][bn] = bv.w;
            } else {
                *reinterpret_cast<float4*>(&Bs[nb][brow][bmap(bcol)]) = bv;
            }
        }
        __syncthreads();
        buf ^= 1;
    }

    float auxv[TN];
    if (EPI < 2) {
#pragma unroll
        for (int j = 0; j < TN; j++) auxv[j] = auxp[colBase + tx * TN + j];
    }
#pragma unroll
    for (int i = 0; i < TM; i++) {
        float* cp = C + (ll)(rowBase + ty * TM + i) * ldc + colBase + tx * TN;
        float o[TN];
#pragma unroll
        for (int j = 0; j < TN; j++) {
            float vv;
            if (F2) {
                const ull p = acc2[i][j >> 1];
                vv = (j & 1) ? __uint_as_float((unsigned)(p >> 32))
                             : __uint_as_float((unsigned)p);
            } else {
                vv = accs[i][j];
            }
            if (EPI == 0)      vv = vv + auxv[j];
            else if (EPI == 1) vv = vv * alpha + auxv[j];
            o[j] = vv;
        }
        *reinterpret_cast<float4*>(cp)     = make_float4(o[0], o[1], o[2], o[3]);
        *reinterpret_cast<float4*>(cp + 4) = make_float4(o[4], o[5], o[6], o[7]);
    }
}

// ---- wrappers: each variant gated on the f32x2 health flag ------------------
template <bool F2>
__global__ __launch_bounds__(256)
void qkv_kernel(const float* __restrict__ hs,
                const float* __restrict__ Wq, const float* __restrict__ bq,
                const float* __restrict__ Wk, const float* __restrict__ bk,
                const float* __restrict__ Wv, const float* __restrict__ bv)
{
    if ((g_useF2 != 0) != F2) return;
    const int z = blockIdx.z;
    const float* W    = (z == 0) ? Wq : (z == 1) ? Wk : Wv;
    const float* bias = (z == 0) ? bq : (z == 1) ? bk : bv;
    float* out        = (z == 0) ? g_q : (z == 1) ? g_k : g_v;
    sgemm_body<true, 0, F2>(hs, W, out, H_, H_, H_, H_, bias, 1.0f);
}

template <bool F2>
__global__ __launch_bounds__(256)
void scores_kernel(float alpha)
{
    if ((g_useF2 != 0) != F2) return;
    const int bz = blockIdx.z;
    sgemm_body<true, 1, F2>(g_q + (ll)bz * S_ * H_, g_k + (ll)bz * S_ * H_,
                            g_scores + (ll)bz * S_ * S_,
                            H_, H_, H_, S_, g_colbias + bz * S_, alpha);
}

template <bool F2>
__global__ __launch_bounds__(256)
void pv_kernel(float* __restrict__ out)
{
    if ((g_useF2 != 0) != F2) return;
    const int bz = blockIdx.z;
    sgemm_body<false, 2, F2>(g_scores + (ll)bz * S_ * S_, g_v + (ll)bz * S_ * H_,
                             out + (ll)bz * S_ * H_,
                             S_, S_, H_, H_, nullptr, 1.0f);
}

// ---------------------------------------------------------------------------
// Row softmax over S_=4096 columns. One block per row, values in registers.
// ---------------------------------------------------------------------------
__global__ __launch_bounds__(256) void softmax_rows()
{
    const ll row = blockIdx.x;
    float4* p4 = reinterpret_cast<float4*>(g_scores + row * (ll)S_);
    const int t = threadIdx.x;
    const int lane = t & 31, w = t >> 5;

    float4 v[4];
    float m = -1e30f;
#pragma unroll
    for (int i = 0; i < 4; i++) {
        v[i] = p4[t + i * 256];
        m = fmaxf(m, fmaxf(fmaxf(v[i].x, v[i].y), fmaxf(v[i].z, v[i].w)));
    }

    __shared__ float sh[8];
    __shared__ float bres;
#pragma unroll
    for (int o = 16; o; o >>= 1) m = fmaxf(m, __shfl_xor_sync(0xffffffffu, m, o));
    if (!lane) sh[w] = m;
    __syncthreads();
    if (t == 0) {
        float mm = sh[0];
#pragma unroll
        for (int i = 1; i < 8; i++) mm = fmaxf(mm, sh[i]);
        bres = mm;
    }
    __syncthreads();
    m = bres;

    float s = 0.f;
#pragma unroll
    for (int i = 0; i < 4; i++) {
        v[i].x = __expf(v[i].x - m); v[i].y = __expf(v[i].y - m);
        v[i].z = __expf(v[i].z - m); v[i].w = __expf(v[i].w - m);
        s += (v[i].x + v[i].y) + (v[i].z + v[i].w);
    }
#pragma unroll
    for (int o = 16; o; o >>= 1) s += __shfl_xor_sync(0xffffffffu, s, o);
    if (!lane) sh[w] = s;
    __syncthreads();
    if (t == 0) {
        float ss = 0.f;
#pragma unroll
        for (int i = 0; i < 8; i++) ss += sh[i];
        bres = ss;
    }
    __syncthreads();
    const float inv = 1.0f / bres;
#pragma unroll
    for (int i = 0; i < 4; i++) {
        v[i].x *= inv; v[i].y *= inv; v[i].z *= inv; v[i].w *= inv;
        p4[t + i * 256] = v[i];
    }
}

// ---------------------------------------------------------------------------
extern "C" void kernel_launch(void* const* d_in, const int* in_sizes, int n_in,
                              void* d_out, int out_size)
{
    const float* hs   = (const float*)d_in[0];
    const float* mask = (const float*)d_in[1];
    const int*   epos = (const int*)d_in[2];
    const float* Wq   = (const float*)d_in[3];
    const float* bq   = (const float*)d_in[4];
    const float* Wk   = (const float*)d_in[5];
    const float* bk   = (const float*)d_in[6];
    const float* Wv   = (const float*)d_in[7];
    const float* bv   = (const float*)d_in[8];
    float* out = (float*)d_out;

    // 0) probe packed-FFMA2 health
    selftest_f32x2<<<1, 32>>>();

    // 1) column bias
    bias_init_kernel<<<(B_ * S_ + 255) / 256, 256>>>(mask);
    bias_scatter_kernel<<<1, 256>>>(epos);

    const dim3 gQKV(H_ / BN, (B_ * S_) / BM, 3);
    const dim3 gSC(S_ / BN, S_ / BM, B_);
    const dim3 gPV(H_ / BN, S_ / BM, B_);
    const float alpha = 1.0f / sqrtf((float)H_);

    // 2) QKV projections (fused; F2 + scalar variants, flag-gated)
    qkv_kernel<true ><<<gQKV, 256>>>(hs, Wq, bq, Wk, bk, Wv, bv);
    qkv_kernel<false><<<gQKV, 256>>>(hs, Wq, bq, Wk, bk, Wv, bv);

    // 3) scores = (Q Kt)/sqrt(H) + colbias
    scores_kernel<true ><<<gSC, 256>>>(alpha);
    scores_kernel<false><<<gSC, 256>>>(alpha);

    // 4) row softmax (in-place fp32)
    softmax_rows<<<B_ * S_, 256>>>();

    // 5) context = P V -> d_out
    pv_kernel<true ><<<gPV, 256>>>(out);
    pv_kernel<false><<<gPV, 256>>>(out);
}